// round 5
// baseline (speedup 1.0000x reference)
#include <cuda_runtime.h>
#include <math.h>

#define NBLK 128
#define NTHR 256

// shared memory layout (float offsets)
constexpr int O_W1 = 0;            // [64][128]  W1t[d][col] = W1[col][d]
constexpr int O_W2 = 8192;         // [128][128] W2t[d][col] = W2[col][d]
constexpr int O_W3 = 24576;        // [128][64]  W3t[w][d]   = W3[d][w]
constexpr int O_KT = 32768;        // [64][64]   Kt[d2][d]
constexpr int O_B1 = 36864;        // [128]
constexpr int O_B2 = 36992;        // [128]
constexpr int O_B3 = 37120;        // [64]
constexpr int O_TS = 37184;        // [128]
constexpr int O_YS = 37312;        // [64][36]  z transposed (feature, row), pad 36
constexpr int O_H1 = 39616;        // [128][36]
constexpr int O_H2 = 44224;        // [128][36]
constexpr int SM_FLOATS = 48832;
constexpr int SMEM_BYTES = SM_FLOATS * 4;   // 195,328 B

__device__ float gW1t[64 * 128];
__device__ float gW2t[128 * 128];
__device__ float gW3t[128 * 64];
__device__ float gKt[64 * 64];

__global__ void setup_kernel(const float* __restrict__ W1, const float* __restrict__ W2,
                             const float* __restrict__ W3, const float* __restrict__ kvec,
                             const float* __restrict__ S, const int* __restrict__ sub) {
    int idx = blockIdx.x * blockDim.x + threadIdx.x;
    int stride = gridDim.x * blockDim.x;
    for (int i = idx; i < 64 * 128; i += stride) {       // W1 [128,64] -> W1t[d][col]
        int d = i >> 7, c = i & 127;
        gW1t[i] = W1[c * 64 + d];
    }
    for (int i = idx; i < 128 * 128; i += stride) {      // W2 [128,128] -> W2t[d][col]
        int d = i >> 7, c = i & 127;
        gW2t[i] = W2[c * 128 + d];
    }
    for (int i = idx; i < 128 * 64; i += stride) {       // W3 [64,128] -> W3t[w][d]
        int w = i >> 6, d = i & 63;
        gW3t[i] = W3[d * 128 + w];
    }
    // Kt[d2][d] = sum_{r: sub[r]==d2} S[d][r]*k[r]   (kin = z @ Kt)
    for (int i = idx; i < 64 * 64; i += stride) {
        int d2 = i >> 6, d = i & 63;
        float acc = 0.f;
        for (int r = 0; r < 128; ++r)
            if (sub[r] == d2) acc = fmaf(S[d * 128 + r], kvec[r], acc);
        gKt[i] = acc;
    }
}

// ---------- packed fp32x2 helpers ----------
__device__ __forceinline__ unsigned long long dup2(float x) {
    unsigned long long r;
    asm("mov.b64 %0, {%1, %1};" : "=l"(r) : "f"(x));
    return r;
}
__device__ __forceinline__ void ffma2(unsigned long long& d, unsigned long long a,
                                      unsigned long long b) {
    asm("fma.rn.f32x2 %0, %1, %2, %0;" : "+l"(d) : "l"(a), "l"(b));
}
__device__ __forceinline__ float2 unpk(unsigned long long v) {
    float2 f;
    asm("mov.b64 {%0, %1}, %2;" : "=f"(f.x), "=f"(f.y) : "l"(v));
    return f;
}
// tanh(x) = 1 - 2/(e^{2x}+1) via MUFU ex2/rcp; rel err ~1e-6
__device__ __forceinline__ float ftanh(float x) {
    float e, r;
    asm("ex2.approx.f32 %0, %1;" : "=f"(e) : "f"(x * 2.8853900817779268f));
    asm("rcp.approx.f32 %0, %1;" : "=f"(r) : "f"(e + 1.0f));
    return fmaf(-2.0f, r, 1.0f);
}

struct F8 { float v[8]; };

// hidden GEMM: thread handles rows r0..r0+7 (rows packed in f32x2), cols {ch, ch+1}
// Lane map guarantees: acts LDS.128 = 4 distinct 16B chunks (1 phase),
// weight LDS.64 = 8 distinct 8B (1 phase).
__device__ __forceinline__ void gemm_hidden(const float* __restrict__ aT,
                                            const float* __restrict__ Wp,
                                            const float* __restrict__ bp,
                                            float* __restrict__ dstT,
                                            int K, int ch, int r0) {
    unsigned long long a0[4], a1[4];
    {
        unsigned long long b0 = dup2(bp[ch]);
        unsigned long long b1 = dup2(bp[ch + 1]);
#pragma unroll
        for (int p = 0; p < 4; ++p) { a0[p] = b0; a1[p] = b1; }
    }
    const float* wptr = Wp + ch;
#pragma unroll 8
    for (int d = 0; d < K; ++d) {
        ulonglong2 pA = *(const ulonglong2*)(aT + d * 36 + r0);       // rows r0..r0+3
        ulonglong2 pB = *(const ulonglong2*)(aT + d * 36 + r0 + 4);   // rows r0+4..r0+7
        float2 wv = *(const float2*)(wptr + d * 128);
        unsigned long long w0 = dup2(wv.x);
        unsigned long long w1 = dup2(wv.y);
        ffma2(a0[0], pA.x, w0); ffma2(a0[1], pA.y, w0);
        ffma2(a0[2], pB.x, w0); ffma2(a0[3], pB.y, w0);
        ffma2(a1[0], pA.x, w1); ffma2(a1[1], pA.y, w1);
        ffma2(a1[2], pB.x, w1); ffma2(a1[3], pB.y, w1);
    }
    {
        float* dst = dstT + ch * 36 + r0;
        float2 f0 = unpk(a0[0]), f1 = unpk(a0[1]), f2 = unpk(a0[2]), f3 = unpk(a0[3]);
        float4 o0 = { ftanh(f0.x), ftanh(f0.y), ftanh(f1.x), ftanh(f1.y) };
        float4 o1 = { ftanh(f2.x), ftanh(f2.y), ftanh(f3.x), ftanh(f3.y) };
        *(float4*)dst = o0;
        *(float4*)(dst + 4) = o1;
    }
    {
        float* dst = dstT + (ch + 1) * 36 + r0;
        float2 f0 = unpk(a1[0]), f1 = unpk(a1[1]), f2 = unpk(a1[2]), f3 = unpk(a1[3]);
        float4 o0 = { ftanh(f0.x), ftanh(f0.y), ftanh(f1.x), ftanh(f1.y) };
        float4 o1 = { ftanh(f2.x), ftanh(f2.y), ftanh(f3.x), ftanh(f3.y) };
        *(float4*)dst = o0;
        *(float4*)(dst + 4) = o1;
    }
}

// full vector field; z already staged in ysT (+synced).
// returns node+kin for rows r0..r0+7, col c3.
__device__ __noinline__ F8 vf_eval(int ch, int c3, int r0) {
    extern __shared__ float sm[];
    const float* ys = sm + O_YS;
    float* h1 = sm + O_H1;
    float* h2 = sm + O_H2;

    gemm_hidden(ys, sm + O_W1, sm + O_B1, h1, 64, ch, r0);
    __syncthreads();
    gemm_hidden(h1, sm + O_W2, sm + O_B2, h2, 128, ch, r0);
    __syncthreads();

    // output GEMM: node = h2 @ W3^T + b3 (K=128); kin = z @ Kt (K=64)
    unsigned long long acc[4];
    {
        unsigned long long b = dup2(sm[O_B3 + c3]);
#pragma unroll
        for (int p = 0; p < 4; ++p) acc[p] = b;
    }
#pragma unroll 8
    for (int w = 0; w < 128; ++w) {
        ulonglong2 pA = *(const ulonglong2*)(h2 + w * 36 + r0);
        ulonglong2 pB = *(const ulonglong2*)(h2 + w * 36 + r0 + 4);
        unsigned long long wd = dup2(sm[O_W3 + w * 64 + c3]);
        ffma2(acc[0], pA.x, wd); ffma2(acc[1], pA.y, wd);
        ffma2(acc[2], pB.x, wd); ffma2(acc[3], pB.y, wd);
    }
#pragma unroll 8
    for (int d2 = 0; d2 < 64; ++d2) {
        ulonglong2 pA = *(const ulonglong2*)(ys + d2 * 36 + r0);
        ulonglong2 pB = *(const ulonglong2*)(ys + d2 * 36 + r0 + 4);
        unsigned long long wd = dup2(sm[O_KT + d2 * 64 + c3]);
        ffma2(acc[0], pA.x, wd); ffma2(acc[1], pA.y, wd);
        ffma2(acc[2], pB.x, wd); ffma2(acc[3], pB.y, wd);
    }
    F8 r;
#pragma unroll
    for (int p = 0; p < 4; ++p) {
        float2 f = unpk(acc[p]);
        r.v[2 * p] = f.x;
        r.v[2 * p + 1] = f.y;
    }
    return r;
}

template <typename F>
__device__ __forceinline__ void write_z(int c3, int r0, F f) {
    extern __shared__ float sm[];
    float* dst = sm + O_YS + c3 * 36 + r0;
    float4 z0, z1;
    z0.x = f(0); z0.y = f(1); z0.z = f(2); z0.w = f(3);
    z1.x = f(4); z1.y = f(5); z1.z = f(6); z1.w = f(7);
    *(float4*)dst = z0;
    *(float4*)(dst + 4) = z1;
}

__global__ void __launch_bounds__(NTHR, 1)
ode_kernel(const float* __restrict__ ts, const float* __restrict__ y0,
           const float* __restrict__ b1g, const float* __restrict__ b2g,
           const float* __restrict__ b3g, float* __restrict__ out) {
    extern __shared__ float sm[];
    int tid = threadIdx.x;

    for (int i = tid; i < 64 * 128; i += NTHR) sm[O_W1 + i] = gW1t[i];
    for (int i = tid; i < 128 * 128; i += NTHR) sm[O_W2 + i] = gW2t[i];
    for (int i = tid; i < 128 * 64; i += NTHR) sm[O_W3 + i] = gW3t[i];
    for (int i = tid; i < 64 * 64; i += NTHR) sm[O_KT + i] = gKt[i];
    if (tid < 128) {
        sm[O_B1 + tid] = b1g[tid];
        sm[O_B2 + tid] = b2g[tid];
        sm[O_TS + tid] = ts[tid];
    }
    if (tid < 64) sm[O_B3 + tid] = b3g[tid];

    // lane map: rl = rowgroup (4 x 8 rows), cl = colgroup (8)
    const int wid = tid >> 5;
    const int lane = tid & 31;
    const int rl = lane & 3;
    const int cl = lane >> 2;
    const int r0 = rl * 8;                 // local rows r0..r0+7
    const int ch = wid * 16 + cl * 2;      // hidden col pair base (0..126)
    const int c3 = wid * 8 + cl;           // output col (0..63)
    const int gm0 = blockIdx.x * 32 + r0;  // global row base

    float y[8];
#pragma unroll
    for (int i = 0; i < 8; ++i) {
        float v = y0[(gm0 + i) * 64 + c3];
        y[i] = v;
        out[(size_t)(gm0 + i) * 64 + c3] = v;   // slice 0 = y0
    }
    __syncthreads();

    for (int iv = 0; iv < 127; ++iv) {
        const float dtS = (sm[O_TS + iv + 1] - sm[O_TS + iv]) * 0.25f;

        for (int ss = 0; ss < 4; ++ss) {
            write_z(c3, r0, [&](int i) { return y[i]; });
            __syncthreads();
            F8 K1 = vf_eval(ch, c3, r0);
            __syncthreads();

            write_z(c3, r0, [&](int i) {
                return fmaf(dtS, 0.161f * K1.v[i], y[i]);
            });
            __syncthreads();
            F8 K2 = vf_eval(ch, c3, r0);
            __syncthreads();

            write_z(c3, r0, [&](int i) {
                float s = fmaf(-0.008480655492356989f, K1.v[i],
                               0.335480655492357f * K2.v[i]);
                return fmaf(dtS, s, y[i]);
            });
            __syncthreads();
            F8 K3 = vf_eval(ch, c3, r0);
            __syncthreads();

            write_z(c3, r0, [&](int i) {
                float s = 2.8971530571054935f * K1.v[i];
                s = fmaf(-6.359448489975075f, K2.v[i], s);
                s = fmaf(4.3622954328695815f, K3.v[i], s);
                return fmaf(dtS, s, y[i]);
            });
            __syncthreads();
            F8 K4 = vf_eval(ch, c3, r0);
            __syncthreads();

            write_z(c3, r0, [&](int i) {
                float s = 5.325864828439257f * K1.v[i];
                s = fmaf(-11.748883564062828f, K2.v[i], s);
                s = fmaf(7.4955393428898365f, K3.v[i], s);
                s = fmaf(-0.09249506636175525f, K4.v[i], s);
                return fmaf(dtS, s, y[i]);
            });
            __syncthreads();
            F8 K5 = vf_eval(ch, c3, r0);
            __syncthreads();

            write_z(c3, r0, [&](int i) {
                float s = 5.86145544294642f * K1.v[i];
                s = fmaf(-12.92096931784711f, K2.v[i], s);
                s = fmaf(8.159367898576159f, K3.v[i], s);
                s = fmaf(-0.071584973281401f, K4.v[i], s);
                s = fmaf(-0.028269050394068383f, K5.v[i], s);
                return fmaf(dtS, s, y[i]);
            });
            __syncthreads();
            F8 K6 = vf_eval(ch, c3, r0);
            __syncthreads();

#pragma unroll
            for (int i = 0; i < 8; ++i) {
                float s = 0.09646076681806523f * K1.v[i];
                s = fmaf(0.01f, K2.v[i], s);
                s = fmaf(0.4798896504144996f, K3.v[i], s);
                s = fmaf(1.379008574103742f, K4.v[i], s);
                s = fmaf(-3.290069515436081f, K5.v[i], s);
                s = fmaf(2.324710524099774f, K6.v[i], s);
                y[i] = fmaf(dtS, s, y[i]);
            }
        }

        size_t base = (size_t)(iv + 1) * 4096 * 64;
#pragma unroll
        for (int i = 0; i < 8; ++i)
            out[base + (gm0 + i) * 64 + c3] = y[i];
    }
}

extern "C" void kernel_launch(void* const* d_in, const int* in_sizes, int n_in,
                              void* d_out, int out_size) {
    const float* ts = (const float*)d_in[0];
    const float* y0 = (const float*)d_in[1];
    const float* W1 = (const float*)d_in[2];
    const float* b1 = (const float*)d_in[3];
    const float* W2 = (const float*)d_in[4];
    const float* b2 = (const float*)d_in[5];
    const float* W3 = (const float*)d_in[6];
    const float* b3 = (const float*)d_in[7];
    const float* k  = (const float*)d_in[8];
    const float* S  = (const float*)d_in[9];
    const int*   sub = (const int*)d_in[10];
    float* out = (float*)d_out;

    static bool attr_done = false;
    if (!attr_done) {
        cudaFuncSetAttribute(ode_kernel,
                             cudaFuncAttributeMaxDynamicSharedMemorySize,
                             SMEM_BYTES);
        attr_done = true;
    }

    setup_kernel<<<64, 256>>>(W1, W2, W3, k, S, sub);
    ode_kernel<<<NBLK, NTHR, SMEM_BYTES>>>(ts, y0, b1, b2, b3, out);
}

// round 6
// speedup vs baseline: 1.6894x; 1.6894x over previous
#include <cuda_runtime.h>
#include <math.h>

#define NBLK 128
#define NTHR 256

// shared memory layout (float offsets)
constexpr int O_W1 = 0;            // [64][128]  W1t[d][col] = W1[col][d]
constexpr int O_W2 = 8192;         // [128][128] W2t[d][col] = W2[col][d]
constexpr int O_W3 = 24576;        // [128][64]  W3t[w][d]   = W3[d][w]
constexpr int O_KT = 32768;        // [64][64]   Kt[d2][d]
constexpr int O_B1 = 36864;        // [128]
constexpr int O_B2 = 36992;        // [128]
constexpr int O_B3 = 37120;        // [64]
constexpr int O_TS = 37184;        // [128]
constexpr int O_YS = 37312;        // [64][36]  z transposed (feature, row), pad 36
constexpr int O_H1 = 39616;        // [128][36]
constexpr int O_H2 = 44224;        // [128][36]
constexpr int SM_FLOATS = 48832;
constexpr int SMEM_BYTES = SM_FLOATS * 4;   // 195,328 B

__device__ float gW1t[64 * 128];
__device__ float gW2t[128 * 128];
__device__ float gW3t[128 * 64];
__device__ float gKt[64 * 64];

__global__ void setup_kernel(const float* __restrict__ W1, const float* __restrict__ W2,
                             const float* __restrict__ W3, const float* __restrict__ kvec,
                             const float* __restrict__ S, const int* __restrict__ sub) {
    int idx = blockIdx.x * blockDim.x + threadIdx.x;
    int stride = gridDim.x * blockDim.x;
    for (int i = idx; i < 64 * 128; i += stride) {       // W1 [128,64] -> W1t[d][col]
        int d = i >> 7, c = i & 127;
        gW1t[i] = W1[c * 64 + d];
    }
    for (int i = idx; i < 128 * 128; i += stride) {      // W2 [128,128] -> W2t[d][col]
        int d = i >> 7, c = i & 127;
        gW2t[i] = W2[c * 128 + d];
    }
    for (int i = idx; i < 128 * 64; i += stride) {       // W3 [64,128] -> W3t[w][d]
        int w = i >> 6, d = i & 63;
        gW3t[i] = W3[d * 128 + w];
    }
    // Kt[d2][d] = sum_{r: sub[r]==d2} S[d][r]*k[r]   (kin = z @ Kt)
    for (int i = idx; i < 64 * 64; i += stride) {
        int d2 = i >> 6, d = i & 63;
        float acc = 0.f;
        for (int r = 0; r < 128; ++r)
            if (sub[r] == d2) acc = fmaf(S[d * 128 + r], kvec[r], acc);
        gKt[i] = acc;
    }
}

// ---------- packed fp32x2 helpers ----------
__device__ __forceinline__ unsigned long long dup2(float x) {
    unsigned long long r;
    asm("mov.b64 %0, {%1, %1};" : "=l"(r) : "f"(x));
    return r;
}
__device__ __forceinline__ void ffma2(unsigned long long& d, unsigned long long a,
                                      unsigned long long b) {
    asm("fma.rn.f32x2 %0, %1, %2, %0;" : "+l"(d) : "l"(a), "l"(b));
}
__device__ __forceinline__ float2 unpk(unsigned long long v) {
    float2 f;
    asm("mov.b64 {%0, %1}, %2;" : "=f"(f.x), "=f"(f.y) : "l"(v));
    return f;
}
// tanh(x) = 1 - 2/(e^{2x}+1) via MUFU ex2/rcp; rel err ~1e-6
__device__ __forceinline__ float ftanh(float x) {
    float e, r;
    asm("ex2.approx.f32 %0, %1;" : "=f"(e) : "f"(x * 2.8853900817779268f));
    asm("rcp.approx.f32 %0, %1;" : "=f"(r) : "f"(e + 1.0f));
    return fmaf(-2.0f, r, 1.0f);
}

// named barrier over one warp-pair (64 threads). ids 1..4.
__device__ __forceinline__ void pbar(int id) {
    asm volatile("bar.sync %0, 64;" :: "r"(id) : "memory");
}

struct F8 { float v[8]; };

// hidden GEMM (no kin): rows r0..r0+7 (warp-uniform -> uniform LDS), cols {ch, ch+1}
__device__ __forceinline__ void gemm_hidden(const float* __restrict__ aT,
                                            const float* __restrict__ Wp,
                                            const float* __restrict__ bp,
                                            float* __restrict__ dstT,
                                            int K, int ch, int r0) {
    unsigned long long a0[4], a1[4];
    {
        unsigned long long b0 = dup2(bp[ch]);
        unsigned long long b1 = dup2(bp[ch + 1]);
#pragma unroll
        for (int p = 0; p < 4; ++p) { a0[p] = b0; a1[p] = b1; }
    }
    const float* wptr = Wp + ch;
#pragma unroll 8
    for (int d = 0; d < K; ++d) {
        ulonglong2 pA = *(const ulonglong2*)(aT + d * 36 + r0);       // uniform
        ulonglong2 pB = *(const ulonglong2*)(aT + d * 36 + r0 + 4);   // uniform
        float2 wv = *(const float2*)(wptr + d * 128);
        unsigned long long w0 = dup2(wv.x);
        unsigned long long w1 = dup2(wv.y);
        ffma2(a0[0], pA.x, w0); ffma2(a0[1], pA.y, w0);
        ffma2(a0[2], pB.x, w0); ffma2(a0[3], pB.y, w0);
        ffma2(a1[0], pA.x, w1); ffma2(a1[1], pA.y, w1);
        ffma2(a1[2], pB.x, w1); ffma2(a1[3], pB.y, w1);
    }
    {
        float* dst = dstT + ch * 36 + r0;
        float2 f0 = unpk(a0[0]), f1 = unpk(a0[1]), f2 = unpk(a0[2]), f3 = unpk(a0[3]);
        float4 o0 = { ftanh(f0.x), ftanh(f0.y), ftanh(f1.x), ftanh(f1.y) };
        float4 o1 = { ftanh(f2.x), ftanh(f2.y), ftanh(f3.x), ftanh(f3.y) };
        *(float4*)dst = o0;
        *(float4*)(dst + 4) = o1;
    }
    {
        float* dst = dstT + (ch + 1) * 36 + r0;
        float2 f0 = unpk(a1[0]), f1 = unpk(a1[1]), f2 = unpk(a1[2]), f3 = unpk(a1[3]);
        float4 o0 = { ftanh(f0.x), ftanh(f0.y), ftanh(f1.x), ftanh(f1.y) };
        float4 o1 = { ftanh(f2.x), ftanh(f2.y), ftanh(f3.x), ftanh(f3.y) };
        *(float4*)dst = o0;
        *(float4*)(dst + 4) = o1;
    }
}

// full vector field, warp-pair private. z already staged in ys slice (+pbar done).
// Folds kin = z@Kt into the G1 loop; only pair barriers inside.
__device__ __noinline__ F8 vf_eval(int ch, int c3, int r0, int bid) {
    extern __shared__ float sm[];
    const float* ys = sm + O_YS;
    float* h1 = sm + O_H1;
    float* h2 = sm + O_H2;

    // ---- G1 (h1 = tanh(z@W1^T+b1)) fused with kin accumulation ----
    unsigned long long a0[4], a1[4], kin[4];
    {
        unsigned long long b0 = dup2(sm[O_B1 + ch]);
        unsigned long long b1 = dup2(sm[O_B1 + ch + 1]);
        unsigned long long b3 = dup2(sm[O_B3 + c3]);
#pragma unroll
        for (int p = 0; p < 4; ++p) { a0[p] = b0; a1[p] = b1; kin[p] = b3; }
    }
    const float* w1ptr = sm + O_W1 + ch;
    const float* ktptr = sm + O_KT + c3;
#pragma unroll 8
    for (int d = 0; d < 64; ++d) {
        ulonglong2 pA = *(const ulonglong2*)(ys + d * 36 + r0);
        ulonglong2 pB = *(const ulonglong2*)(ys + d * 36 + r0 + 4);
        float2 wv = *(const float2*)(w1ptr + d * 128);
        unsigned long long w0 = dup2(wv.x);
        unsigned long long w1 = dup2(wv.y);
        unsigned long long kt = dup2(ktptr[d * 64]);
        ffma2(a0[0], pA.x, w0); ffma2(a0[1], pA.y, w0);
        ffma2(a0[2], pB.x, w0); ffma2(a0[3], pB.y, w0);
        ffma2(a1[0], pA.x, w1); ffma2(a1[1], pA.y, w1);
        ffma2(a1[2], pB.x, w1); ffma2(a1[3], pB.y, w1);
        ffma2(kin[0], pA.x, kt); ffma2(kin[1], pA.y, kt);
        ffma2(kin[2], pB.x, kt); ffma2(kin[3], pB.y, kt);
    }
    {
        float* dst = h1 + ch * 36 + r0;
        float2 f0 = unpk(a0[0]), f1 = unpk(a0[1]), f2 = unpk(a0[2]), f3 = unpk(a0[3]);
        float4 o0 = { ftanh(f0.x), ftanh(f0.y), ftanh(f1.x), ftanh(f1.y) };
        float4 o1 = { ftanh(f2.x), ftanh(f2.y), ftanh(f3.x), ftanh(f3.y) };
        *(float4*)dst = o0;
        *(float4*)(dst + 4) = o1;
    }
    {
        float* dst = h1 + (ch + 1) * 36 + r0;
        float2 f0 = unpk(a1[0]), f1 = unpk(a1[1]), f2 = unpk(a1[2]), f3 = unpk(a1[3]);
        float4 o0 = { ftanh(f0.x), ftanh(f0.y), ftanh(f1.x), ftanh(f1.y) };
        float4 o1 = { ftanh(f2.x), ftanh(f2.y), ftanh(f3.x), ftanh(f3.y) };
        *(float4*)dst = o0;
        *(float4*)(dst + 4) = o1;
    }
    pbar(bid);

    // ---- G2 ----
    gemm_hidden(h1, sm + O_W2, sm + O_B2, h2, 128, ch, r0);
    pbar(bid);

    // ---- G3: node = h2 @ W3^T (+ b3 + kin already in accumulators) ----
#pragma unroll 8
    for (int w = 0; w < 128; ++w) {
        ulonglong2 pA = *(const ulonglong2*)(h2 + w * 36 + r0);
        ulonglong2 pB = *(const ulonglong2*)(h2 + w * 36 + r0 + 4);
        unsigned long long wd = dup2(sm[O_W3 + w * 64 + c3]);
        ffma2(kin[0], pA.x, wd); ffma2(kin[1], pA.y, wd);
        ffma2(kin[2], pB.x, wd); ffma2(kin[3], pB.y, wd);
    }
    F8 r;
#pragma unroll
    for (int p = 0; p < 4; ++p) {
        float2 f = unpk(kin[p]);
        r.v[2 * p] = f.x;
        r.v[2 * p + 1] = f.y;
    }
    return r;
}

template <typename F>
__device__ __forceinline__ void write_z(int c3, int r0, F f) {
    extern __shared__ float sm[];
    float* dst = sm + O_YS + c3 * 36 + r0;
    float4 z0, z1;
    z0.x = f(0); z0.y = f(1); z0.z = f(2); z0.w = f(3);
    z1.x = f(4); z1.y = f(5); z1.z = f(6); z1.w = f(7);
    *(float4*)dst = z0;
    *(float4*)(dst + 4) = z1;
}

__global__ void __launch_bounds__(NTHR, 1)
ode_kernel(const float* __restrict__ ts, const float* __restrict__ y0,
           const float* __restrict__ b1g, const float* __restrict__ b2g,
           const float* __restrict__ b3g, float* __restrict__ out) {
    extern __shared__ float sm[];
    int tid = threadIdx.x;

    for (int i = tid; i < 64 * 128; i += NTHR) sm[O_W1 + i] = gW1t[i];
    for (int i = tid; i < 128 * 128; i += NTHR) sm[O_W2 + i] = gW2t[i];
    for (int i = tid; i < 128 * 64; i += NTHR) sm[O_W3 + i] = gW3t[i];
    for (int i = tid; i < 64 * 64; i += NTHR) sm[O_KT + i] = gKt[i];
    if (tid < 128) {
        sm[O_B1 + tid] = b1g[tid];
        sm[O_B2 + tid] = b2g[tid];
        sm[O_TS + tid] = ts[tid];
    }
    if (tid < 64) sm[O_B3 + tid] = b3g[tid];

    // pair-aligned mapping (same as R3): warp-pair p owns rows 8p..8p+7.
    const int ct = tid & 63;           // 0..63 within pair
    const int ch = 2 * ct;             // hidden col pair base
    const int c3 = ct;                 // output col
    const int r0 = (tid >> 6) * 8;     // local rows r0..r0+7 (warp-uniform)
    const int bid = 1 + (tid >> 6);    // named barrier id 1..4, 64 threads each
    const int gm0 = blockIdx.x * 32 + r0;

    float y[8];
#pragma unroll
    for (int i = 0; i < 8; ++i) {
        float v = y0[(gm0 + i) * 64 + c3];
        y[i] = v;
        out[(size_t)(gm0 + i) * 64 + c3] = v;   // slice 0 = y0
    }
    __syncthreads();   // weights staged + y0 loaded

    for (int iv = 0; iv < 127; ++iv) {
        const float dtS = (sm[O_TS + iv + 1] - sm[O_TS + iv]) * 0.25f;

        for (int ss = 0; ss < 4; ++ss) {
            write_z(c3, r0, [&](int i) { return y[i]; });
            pbar(bid);
            F8 K1 = vf_eval(ch, c3, r0, bid);

            write_z(c3, r0, [&](int i) {
                return fmaf(dtS, 0.161f * K1.v[i], y[i]);
            });
            pbar(bid);
            F8 K2 = vf_eval(ch, c3, r0, bid);

            write_z(c3, r0, [&](int i) {
                float s = fmaf(-0.008480655492356989f, K1.v[i],
                               0.335480655492357f * K2.v[i]);
                return fmaf(dtS, s, y[i]);
            });
            pbar(bid);
            F8 K3 = vf_eval(ch, c3, r0, bid);

            write_z(c3, r0, [&](int i) {
                float s = 2.8971530571054935f * K1.v[i];
                s = fmaf(-6.359448489975075f, K2.v[i], s);
                s = fmaf(4.3622954328695815f, K3.v[i], s);
                return fmaf(dtS, s, y[i]);
            });
            pbar(bid);
            F8 K4 = vf_eval(ch, c3, r0, bid);

            write_z(c3, r0, [&](int i) {
                float s = 5.325864828439257f * K1.v[i];
                s = fmaf(-11.748883564062828f, K2.v[i], s);
                s = fmaf(7.4955393428898365f, K3.v[i], s);
                s = fmaf(-0.09249506636175525f, K4.v[i], s);
                return fmaf(dtS, s, y[i]);
            });
            pbar(bid);
            F8 K5 = vf_eval(ch, c3, r0, bid);

            write_z(c3, r0, [&](int i) {
                float s = 5.86145544294642f * K1.v[i];
                s = fmaf(-12.92096931784711f, K2.v[i], s);
                s = fmaf(8.159367898576159f, K3.v[i], s);
                s = fmaf(-0.071584973281401f, K4.v[i], s);
                s = fmaf(-0.028269050394068383f, K5.v[i], s);
                return fmaf(dtS, s, y[i]);
            });
            pbar(bid);
            F8 K6 = vf_eval(ch, c3, r0, bid);

#pragma unroll
            for (int i = 0; i < 8; ++i) {
                float s = 0.09646076681806523f * K1.v[i];
                s = fmaf(0.01f, K2.v[i], s);
                s = fmaf(0.4798896504144996f, K3.v[i], s);
                s = fmaf(1.379008574103742f, K4.v[i], s);
                s = fmaf(-3.290069515436081f, K5.v[i], s);
                s = fmaf(2.324710524099774f, K6.v[i], s);
                y[i] = fmaf(dtS, s, y[i]);
            }
        }

        size_t base = (size_t)(iv + 1) * 4096 * 64;
#pragma unroll
        for (int i = 0; i < 8; ++i)
            out[base + (gm0 + i) * 64 + c3] = y[i];
    }
}

extern "C" void kernel_launch(void* const* d_in, const int* in_sizes, int n_in,
                              void* d_out, int out_size) {
    const float* ts = (const float*)d_in[0];
    const float* y0 = (const float*)d_in[1];
    const float* W1 = (const float*)d_in[2];
    const float* b1 = (const float*)d_in[3];
    const float* W2 = (const float*)d_in[4];
    const float* b2 = (const float*)d_in[5];
    const float* W3 = (const float*)d_in[6];
    const float* b3 = (const float*)d_in[7];
    const float* k  = (const float*)d_in[8];
    const float* S  = (const float*)d_in[9];
    const int*   sub = (const int*)d_in[10];
    float* out = (float*)d_out;

    static bool attr_done = false;
    if (!attr_done) {
        cudaFuncSetAttribute(ode_kernel,
                             cudaFuncAttributeMaxDynamicSharedMemorySize,
                             SMEM_BYTES);
        attr_done = true;
    }

    setup_kernel<<<64, 256>>>(W1, W2, W3, k, S, sub);
    ode_kernel<<<NBLK, NTHR, SMEM_BYTES>>>(ts, y0, b1, b2, b3, out);
}